// round 1
// baseline (speedup 1.0000x reference)
#include <cuda_runtime.h>
#include <cuda_bf16.h>
#include <math.h>

// ---------------------------------------------------------------------------
// Problem constants
// ---------------------------------------------------------------------------
#define BATCH      32
#define NHEADS     32
#define NKVH       8
#define GRP        4            // NHEADS / NKVH
#define HDIM       128
#define HIDDEN     4096         // NHEADS*HDIM
#define QSIZE      4096
#define KVSIZE     1024
#define QKVN       6144         // QSIZE + 2*KVSIZE
#define PG_BLK     16           // tokens per cache block
#define MAX_BPS    128
#define MAXCTX     2048
#define SPLIT      256          // tokens per attention split
#define NSPLIT     8            // MAXCTX / SPLIT

// ---------------------------------------------------------------------------
// Scratch (no cudaMalloc allowed)
// ---------------------------------------------------------------------------
__device__ float g_qkv_part[2][BATCH][QKVN];      // K-split GEMM partials
__device__ float g_qkv[BATCH][QKVN];              // qkv after bias + rope
__device__ float g_po[BATCH][NKVH][GRP][NSPLIT][HDIM]; // attention split partials
__device__ float g_pm[BATCH][NKVH][GRP][NSPLIT];
__device__ float g_pl[BATCH][NKVH][GRP][NSPLIT];
__device__ float g_attn[BATCH][HIDDEN];           // attention output
__device__ float g_o_part[2][BATCH][HIDDEN];      // O-proj K-split partials

// ---------------------------------------------------------------------------
// Kernel 1/5: tiled SGEMM, C_part[kp] = A[32,Kh] * W[n,Kh]^T  (K split in 2)
//   A: [32, K] row-major, W: [N, K] row-major
//   Cpart: [2][32][N]
// ---------------------------------------------------------------------------
#define GBM 32
#define GBN 64
#define GBK 32
#define WPAD 68   // padded row stride for transposed W tile (float4-aligned)

__global__ __launch_bounds__(256)
void gemm32_part(const float* __restrict__ A, const float* __restrict__ W,
                 float* __restrict__ Cpart, int K, int N) {
    __shared__ float As[GBM][GBK];
    __shared__ float Ws[GBK][WPAD];

    const int n0   = blockIdx.x * GBN;
    const int kp   = blockIdx.y;
    const int klen = K >> 1;
    const int kbeg = kp * klen;

    const int tid = threadIdx.x;
    const int tx  = tid & 15;     // 16 -> 4 cols each
    const int ty  = tid >> 4;     // 16 -> 2 rows each

    float acc[2][4];
#pragma unroll
    for (int r = 0; r < 2; r++)
#pragma unroll
        for (int c = 0; c < 4; c++) acc[r][c] = 0.0f;

    const int arow = tid >> 3, aq = tid & 7;

    for (int k0 = kbeg; k0 < kbeg + klen; k0 += GBK) {
        // Load A tile 32x32 (one float4 per thread)
        float4 av = *(const float4*)(A + (long)arow * K + k0 + aq * 4);
        *(float4*)&As[arow][aq * 4] = av;

        // Load W tile 64x32, store transposed (two float4 per thread)
#pragma unroll
        for (int i = 0; i < 2; i++) {
            int idx = tid + i * 256;
            int wr = idx >> 3, q = idx & 7;
            float4 wv = *(const float4*)(W + (long)(n0 + wr) * K + k0 + q * 4);
            Ws[q * 4 + 0][wr] = wv.x;
            Ws[q * 4 + 1][wr] = wv.y;
            Ws[q * 4 + 2][wr] = wv.z;
            Ws[q * 4 + 3][wr] = wv.w;
        }
        __syncthreads();

#pragma unroll
        for (int kk = 0; kk < GBK; kk++) {
            float a0 = As[ty * 2 + 0][kk];
            float a1 = As[ty * 2 + 1][kk];
            float4 wv = *(const float4*)&Ws[kk][tx * 4];
            acc[0][0] += a0 * wv.x; acc[0][1] += a0 * wv.y;
            acc[0][2] += a0 * wv.z; acc[0][3] += a0 * wv.w;
            acc[1][0] += a1 * wv.x; acc[1][1] += a1 * wv.y;
            acc[1][2] += a1 * wv.z; acc[1][3] += a1 * wv.w;
        }
        __syncthreads();
    }

#pragma unroll
    for (int r = 0; r < 2; r++) {
        int row = ty * 2 + r;
        float4 o = make_float4(acc[r][0], acc[r][1], acc[r][2], acc[r][3]);
        *(float4*)(Cpart + ((long)kp * GBM + row) * N + n0 + tx * 4) = o;
    }
}

// ---------------------------------------------------------------------------
// Kernel 2/5: combine QKV partials + bias, then RoPE on q and k (in place).
// One block per batch row. Heads 0..31 = q, 32..39 = k; all at stride 128.
// ---------------------------------------------------------------------------
__global__ __launch_bounds__(256)
void rope_combine(const float* __restrict__ bias, const int* __restrict__ ctx_lens) {
    const int b = blockIdx.x;
    const int pos = ctx_lens[b] - 1;

    for (int i = threadIdx.x; i < QKVN; i += 256)
        g_qkv[b][i] = g_qkv_part[0][b][i] + g_qkv_part[1][b][i] + bias[i];
    __syncthreads();

    // 40 heads (32 q + 8 k) x 64 rotation pairs
    for (int i = threadIdx.x; i < 40 * 64; i += 256) {
        int hh = i >> 6, d = i & 63;
        float inv = __powf(10000.0f, -(float)d / 64.0f);
        float ang = (float)pos * inv;
        float c, s;
        __sincosf(ang, &s, &c);
        // use precise variants for rel-err safety at large angles
        c = cosf(ang); s = sinf(ang);
        int base = hh * HDIM;
        float x1 = g_qkv[b][base + d];
        float x2 = g_qkv[b][base + 64 + d];
        g_qkv[b][base + d]      = x1 * c - x2 * s;
        g_qkv[b][base + 64 + d] = x2 * c + x1 * s;
    }
}

// ---------------------------------------------------------------------------
// Kernel 3/5: flash-decode attention over context splits.
// grid = (NSPLIT, NKVH, BATCH), block = 128 (4 warps); warp handles every
// 4th token of the split; 4 query heads (GQA group) per kv head.
// ---------------------------------------------------------------------------
__global__ __launch_bounds__(128)
void attn_split(const float* __restrict__ k_cache, const float* __restrict__ v_cache,
                const int* __restrict__ block_tables, const int* __restrict__ ctx_lens) {
    const int b = blockIdx.z, kvh = blockIdx.y, split = blockIdx.x;
    const int ctx = ctx_lens[b];
    const int start = split * SPLIT;
    if (start >= ctx) return;
    const int end = min(start + SPLIT, ctx);
    const int pos = ctx - 1;

    __shared__ float qs[GRP][HDIM];
    __shared__ float sm[4][GRP], sl[4][GRP];
    __shared__ float sacc[4][GRP][HDIM];

    const int tid  = threadIdx.x;
    const int lane = tid & 31;
    const int w    = tid >> 5;

    for (int i = tid; i < GRP * HDIM; i += 128) {
        int g = i >> 7, d = i & 127;
        qs[g][d] = g_qkv[b][(kvh * GRP + g) * HDIM + d];
    }
    __syncthreads();

    float4 qreg[GRP];
#pragma unroll
    for (int g = 0; g < GRP; g++) qreg[g] = *(const float4*)&qs[g][lane * 4];

    const int* bt = block_tables + b * MAX_BPS;
    const float scale = 0.08838834764831845f; // 128^-0.5

    float m[GRP], l[GRP];
    float4 acc[GRP];
#pragma unroll
    for (int g = 0; g < GRP; g++) {
        m[g] = -INFINITY; l[g] = 0.0f;
        acc[g] = make_float4(0.f, 0.f, 0.f, 0.f);
    }

    for (int t = start + w; t < end; t += 4) {
        const float* kptr;
        const float* vptr;
        if (t == pos) {
            kptr = &g_qkv[b][QSIZE + kvh * HDIM];
            vptr = &g_qkv[b][QSIZE + KVSIZE + kvh * HDIM];
        } else {
            int blk = bt[t >> 4];
            long off = (((long)blk * PG_BLK + (t & 15)) * NKVH + kvh) * HDIM;
            kptr = k_cache + off;
            vptr = v_cache + off;
        }
        float4 kv = *(const float4*)(kptr + lane * 4);
        float s[GRP];
#pragma unroll
        for (int g = 0; g < GRP; g++) {
            float p = kv.x * qreg[g].x + kv.y * qreg[g].y +
                      kv.z * qreg[g].z + kv.w * qreg[g].w;
            p += __shfl_xor_sync(0xffffffff, p, 16);
            p += __shfl_xor_sync(0xffffffff, p, 8);
            p += __shfl_xor_sync(0xffffffff, p, 4);
            p += __shfl_xor_sync(0xffffffff, p, 2);
            p += __shfl_xor_sync(0xffffffff, p, 1);
            s[g] = p * scale;
        }
        float4 vv = *(const float4*)(vptr + lane * 4);
#pragma unroll
        for (int g = 0; g < GRP; g++) {
            float mn = fmaxf(m[g], s[g]);
            float corr = __expf(m[g] - mn);
            float p = __expf(s[g] - mn);
            l[g] = l[g] * corr + p;
            acc[g].x = acc[g].x * corr + p * vv.x;
            acc[g].y = acc[g].y * corr + p * vv.y;
            acc[g].z = acc[g].z * corr + p * vv.z;
            acc[g].w = acc[g].w * corr + p * vv.w;
            m[g] = mn;
        }
    }

#pragma unroll
    for (int g = 0; g < GRP; g++) {
        if (lane == 0) { sm[w][g] = m[g]; sl[w][g] = l[g]; }
        *(float4*)&sacc[w][g][lane * 4] = acc[g];
    }
    __syncthreads();

    // 128 threads: thread d finalizes dim d for each head in the group
    const int d = tid;
#pragma unroll
    for (int g = 0; g < GRP; g++) {
        float M = fmaxf(fmaxf(sm[0][g], sm[1][g]), fmaxf(sm[2][g], sm[3][g]));
        float L = 0.f, O = 0.f;
#pragma unroll
        for (int ww = 0; ww < 4; ww++) {
            float c = __expf(sm[ww][g] - M);
            L += sl[ww][g] * c;
            O += sacc[ww][g][d] * c;
        }
        g_po[b][kvh][g][split][d] = O;
        if (d == 0) { g_pm[b][kvh][g][split] = M; g_pl[b][kvh][g][split] = L; }
    }
}

// ---------------------------------------------------------------------------
// Kernel 4/5: combine context splits (log-sum-exp merge) -> g_attn
// grid = (NKVH, BATCH), block = 128
// ---------------------------------------------------------------------------
__global__ __launch_bounds__(128)
void attn_combine(const int* __restrict__ ctx_lens) {
    const int kvh = blockIdx.x, b = blockIdx.y;
    const int ctx = ctx_lens[b];
    const int ns  = (ctx + SPLIT - 1) / SPLIT;
    const int d   = threadIdx.x;

#pragma unroll
    for (int g = 0; g < GRP; g++) {
        float M = -INFINITY;
        for (int s = 0; s < ns; s++) M = fmaxf(M, g_pm[b][kvh][g][s]);
        float L = 0.f, O = 0.f;
        for (int s = 0; s < ns; s++) {
            float c = __expf(g_pm[b][kvh][g][s] - M);
            L += g_pl[b][kvh][g][s] * c;
            O += g_po[b][kvh][g][s][d] * c;
        }
        g_attn[b][(kvh * GRP + g) * HDIM + d] = O / L;
    }
}

// ---------------------------------------------------------------------------
// Kernel 5/5: epilogue — sum O-proj K-split partials + bias -> d_out
// ---------------------------------------------------------------------------
__global__ __launch_bounds__(256)
void oproj_epilogue(const float* __restrict__ b_o, float* __restrict__ out) {
    int i = blockIdx.x * 256 + threadIdx.x;
    if (i >= BATCH * HIDDEN) return;
    int n = i & (HIDDEN - 1);
    out[i] = g_o_part[0][0][i] + g_o_part[1][0][i] + b_o[n];
}

// ---------------------------------------------------------------------------
// Launcher
// ---------------------------------------------------------------------------
extern "C" void kernel_launch(void* const* d_in, const int* in_sizes, int n_in,
                              void* d_out, int out_size) {
    const float* hidden   = (const float*)d_in[0];
    const float* W_qkv    = (const float*)d_in[1];
    const float* b_qkv    = (const float*)d_in[2];
    const float* W_o      = (const float*)d_in[3];
    const float* b_o      = (const float*)d_in[4];
    const float* k_cache  = (const float*)d_in[5];
    const float* v_cache  = (const float*)d_in[6];
    const int*   btables  = (const int*)d_in[7];
    const int*   ctx_lens = (const int*)d_in[8];
    float* out = (float*)d_out;

    float *qkv_part_ptr, *attn_ptr, *o_part_ptr;
    cudaGetSymbolAddress((void**)&qkv_part_ptr, g_qkv_part);
    cudaGetSymbolAddress((void**)&attn_ptr,     g_attn);
    cudaGetSymbolAddress((void**)&o_part_ptr,   g_o_part);

    // 1) QKV projection (K split in 2): 96x2 blocks
    gemm32_part<<<dim3(QKVN / GBN, 2), 256>>>(hidden, W_qkv, qkv_part_ptr, HIDDEN, QKVN);

    // 2) bias + RoPE
    rope_combine<<<BATCH, 256>>>(b_qkv, ctx_lens);

    // 3) flash-decode attention over splits
    attn_split<<<dim3(NSPLIT, NKVH, BATCH), 128>>>(k_cache, v_cache, btables, ctx_lens);

    // 4) split combine
    attn_combine<<<dim3(NKVH, BATCH), 128>>>(ctx_lens);

    // 5) O projection (K split in 2): 64x2 blocks
    gemm32_part<<<dim3(HIDDEN / GBN, 2), 256>>>(attn_ptr, W_o, o_part_ptr, HIDDEN, HIDDEN);

    // 6) epilogue
    oproj_epilogue<<<(BATCH * HIDDEN + 255) / 256, 256>>>(b_o, out);
}

// round 2
// speedup vs baseline: 1.5080x; 1.5080x over previous
#include <cuda_runtime.h>
#include <math.h>

// ---------------------------------------------------------------------------
// Problem constants
// ---------------------------------------------------------------------------
#define BATCH      32
#define NKVH       8
#define GRP        4
#define HDIM       128
#define HIDDEN     4096
#define QSIZE      4096
#define KVSIZE     1024
#define QKVN       6144
#define PG_BLK     16
#define MAX_BPS    128
#define SPLIT      128
#define NSPLIT     16           // MAXCTX / SPLIT
#define KSPLIT     16           // GEMM split-K factor

// ---------------------------------------------------------------------------
// Scratch (no cudaMalloc allowed)
// ---------------------------------------------------------------------------
__device__ float g_qkv_part[KSPLIT][BATCH][QKVN];
__device__ float g_qkv[BATCH][QKVN];
__device__ float g_po[BATCH][NKVH][GRP][NSPLIT][HDIM];
__device__ float g_pm[BATCH][NKVH][GRP][NSPLIT];
__device__ float g_pl[BATCH][NKVH][GRP][NSPLIT];
__device__ float g_attn[BATCH][HIDDEN];
__device__ float g_o_part[KSPLIT][BATCH][HIDDEN];

// ---------------------------------------------------------------------------
// f32x2 packed-FMA helpers (FFMA2 — only reachable via PTX)
// ---------------------------------------------------------------------------
__device__ __forceinline__ unsigned long long bc2(float x) {
    unsigned long long r;
    asm("mov.b64 %0, {%1, %1};" : "=l"(r) : "f"(x));
    return r;
}
__device__ __forceinline__ void ffma2(unsigned long long& d,
                                      unsigned long long a, unsigned long long b) {
    asm("fma.rn.f32x2 %0, %1, %2, %0;" : "+l"(d) : "l"(a), "l"(b));
}
__device__ __forceinline__ float2 unpk(unsigned long long r) {
    float2 f;
    asm("mov.b64 {%0, %1}, %2;" : "=f"(f.x), "=f"(f.y) : "l"(r));
    return f;
}

// ---------------------------------------------------------------------------
// Skinny GEMM: Cpart[kp] = A[32,Kc] * W[n,Kc]^T   (K split into KSPLIT chunks)
// Block: 32(M) x 64(N) tile, TBK=32, 128 threads, per-thread 4r x 4c in FFMA2,
// register-prefetch double buffering (one sync per k-tile).
// ---------------------------------------------------------------------------
#define TBN 64
#define TBK 32

__global__ __launch_bounds__(128)
void gemm_skinny(const float* __restrict__ A, const float* __restrict__ W,
                 float* __restrict__ Cpart, int K, int N) {
    __shared__ __align__(16) float Ws[2][TBK][TBN];
    __shared__ __align__(16) float As[2][TBK][32];

    const int tid = threadIdx.x;
    const int n0  = blockIdx.x * TBN;
    const int kp  = blockIdx.y;
    const int kchunk = K / KSPLIT;
    const int kbeg   = kp * kchunk;
    const int ntile  = kchunk / TBK;

    // Load mapping: W tile 64x32 -> 4 float4/thread, A tile 32x32 -> 2 float4/thread
    const int wn = tid & 63;            // W row (output col)
    const int wh = tid >> 6;            // k half (0..1)
    const float* wsrc = W + (long)(n0 + wn) * K + kbeg + wh * 16;
    const int ar = tid & 31;            // A row
    const int aq = tid >> 5;            // 0..3
    const float* asrc = A + (long)ar * K + kbeg + aq * 8;

    const int tx = tid & 15;            // col group (4 cols)
    const int ty = tid >> 4;            // row group (4 rows)

    float4 wreg[4], areg[2];

    // Prologue: load tile 0 into regs
#pragma unroll
    for (int i = 0; i < 4; i++) wreg[i] = *(const float4*)(wsrc + i * 4);
#pragma unroll
    for (int i = 0; i < 2; i++) areg[i] = *(const float4*)(asrc + i * 4);

    // Scalar transposed stores: bank = lane (conflict-free)
#pragma unroll
    for (int i = 0; i < 4; i++) {
        int kl = wh * 16 + i * 4;
        Ws[0][kl + 0][wn] = wreg[i].x; Ws[0][kl + 1][wn] = wreg[i].y;
        Ws[0][kl + 2][wn] = wreg[i].z; Ws[0][kl + 3][wn] = wreg[i].w;
    }
#pragma unroll
    for (int i = 0; i < 2; i++) {
        int kl = aq * 8 + i * 4;
        As[0][kl + 0][ar] = areg[i].x; As[0][kl + 1][ar] = areg[i].y;
        As[0][kl + 2][ar] = areg[i].z; As[0][kl + 3][ar] = areg[i].w;
    }
    __syncthreads();

    unsigned long long acc[2][4];
#pragma unroll
    for (int r = 0; r < 2; r++)
#pragma unroll
        for (int c = 0; c < 4; c++) acc[r][c] = 0ULL;

    int p = 0;
    for (int t = 0; t < ntile; t++) {
        // Prefetch next tile into registers (hidden under compute)
        if (t + 1 < ntile) {
            const float* wp2 = wsrc + (t + 1) * TBK;
            const float* ap2 = asrc + (t + 1) * TBK;
#pragma unroll
            for (int i = 0; i < 4; i++) wreg[i] = *(const float4*)(wp2 + i * 4);
#pragma unroll
            for (int i = 0; i < 2; i++) areg[i] = *(const float4*)(ap2 + i * 4);
        }

        // Compute current tile
#pragma unroll
        for (int kk = 0; kk < TBK; kk++) {
            ulonglong2 a01 = *(const ulonglong2*)&As[p][kk][ty * 4];
            float4 w = *(const float4*)&Ws[p][kk][tx * 4];
            unsigned long long w0 = bc2(w.x), w1 = bc2(w.y),
                               w2 = bc2(w.z), w3 = bc2(w.w);
            ffma2(acc[0][0], a01.x, w0); ffma2(acc[0][1], a01.x, w1);
            ffma2(acc[0][2], a01.x, w2); ffma2(acc[0][3], a01.x, w3);
            ffma2(acc[1][0], a01.y, w0); ffma2(acc[1][1], a01.y, w1);
            ffma2(acc[1][2], a01.y, w2); ffma2(acc[1][3], a01.y, w3);
        }

        // Store next tile into the other buffer
        if (t + 1 < ntile) {
            int q = p ^ 1;
#pragma unroll
            for (int i = 0; i < 4; i++) {
                int kl = wh * 16 + i * 4;
                Ws[q][kl + 0][wn] = wreg[i].x; Ws[q][kl + 1][wn] = wreg[i].y;
                Ws[q][kl + 2][wn] = wreg[i].z; Ws[q][kl + 3][wn] = wreg[i].w;
            }
#pragma unroll
            for (int i = 0; i < 2; i++) {
                int kl = aq * 8 + i * 4;
                As[q][kl + 0][ar] = areg[i].x; As[q][kl + 1][ar] = areg[i].y;
                As[q][kl + 2][ar] = areg[i].z; As[q][kl + 3][ar] = areg[i].w;
            }
        }
        __syncthreads();
        p ^= 1;
    }

    // Epilogue: unpack row-paired accumulators, write 4 rows x 4 cols
#pragma unroll
    for (int rp = 0; rp < 2; rp++) {
        float2 c0 = unpk(acc[rp][0]), c1 = unpk(acc[rp][1]);
        float2 c2 = unpk(acc[rp][2]), c3 = unpk(acc[rp][3]);
        int r0 = ty * 4 + rp * 2;
        float* dst = Cpart + ((long)kp * 32 + r0) * N + n0 + tx * 4;
        *(float4*)dst       = make_float4(c0.x, c1.x, c2.x, c3.x);
        *(float4*)(dst + N) = make_float4(c0.y, c1.y, c2.y, c3.y);
    }
}

// ---------------------------------------------------------------------------
// QKV partial combine + bias + RoPE.  grid=(8 chunks, 32 batch), 256 thr.
// Each chunk = 768 elements = 6 heads (RoPE on heads < 40: q 0..31, k 32..39).
// ---------------------------------------------------------------------------
__global__ __launch_bounds__(256)
void qkv_combine_rope(const float* __restrict__ bias, const int* __restrict__ ctxl) {
    const int c = blockIdx.x, b = blockIdx.y;
    const int base = c * 768;
    const int pos = ctxl[b] - 1;
    __shared__ float s[768];

    for (int i = threadIdx.x; i < 768; i += 256) {
        float v = bias[base + i];
#pragma unroll
        for (int p = 0; p < KSPLIT; p++) v += g_qkv_part[p][b][base + i];
        s[i] = v;
    }
    __syncthreads();

    for (int i = threadIdx.x; i < 384; i += 256) {     // 6 heads x 64 pairs
        int hl = i >> 6, d = i & 63;
        int h = c * 6 + hl;
        if (h < 40) {
            float inv = powf(10000.0f, -(float)d / 64.0f);
            float ang = (float)pos * inv;
            float cs = cosf(ang), sn = sinf(ang);
            float x1 = s[hl * 128 + d], x2 = s[hl * 128 + 64 + d];
            s[hl * 128 + d]      = x1 * cs - x2 * sn;
            s[hl * 128 + 64 + d] = x2 * cs + x1 * sn;
        }
    }
    __syncthreads();

    for (int i = threadIdx.x; i < 768; i += 256) g_qkv[b][base + i] = s[i];
}

// ---------------------------------------------------------------------------
// Flash-decode attention split.  grid=(NSPLIT, NKVH, BATCH), 128 thr (4 warps).
// Warp handles every 4th token, software-pipelined K/V prefetch.
// ---------------------------------------------------------------------------
__global__ __launch_bounds__(128)
void attn_split(const float* __restrict__ k_cache, const float* __restrict__ v_cache,
                const int* __restrict__ btab, const int* __restrict__ ctxl) {
    const int b = blockIdx.z, kvh = blockIdx.y, sp = blockIdx.x;
    const int ctx = ctxl[b];
    const int start = sp * SPLIT;
    if (start >= ctx) return;
    const int end = min(start + SPLIT, ctx);
    const int pos = ctx - 1;

    __shared__ float qs[GRP][HDIM];
    __shared__ int   sbt[8];
    __shared__ float sm[4][GRP], sl[4][GRP];
    __shared__ float sacc[4][GRP][HDIM];

    const int tid = threadIdx.x, lane = tid & 31, w = tid >> 5;

    if (tid < 8) sbt[tid] = btab[b * MAX_BPS + (start >> 4) + tid];
    for (int i = tid; i < GRP * HDIM; i += 128)
        qs[i >> 7][i & 127] = g_qkv[b][(kvh * GRP + (i >> 7)) * HDIM + (i & 127)];
    __syncthreads();

    float4 q[GRP];
#pragma unroll
    for (int g = 0; g < GRP; g++) q[g] = *(const float4*)&qs[g][lane * 4];

    const float scale = 0.08838834764831845f;
    float m[GRP], l[GRP];
    float4 acc[GRP];
#pragma unroll
    for (int g = 0; g < GRP; g++) {
        m[g] = -INFINITY; l[g] = 0.0f;
        acc[g] = make_float4(0.f, 0.f, 0.f, 0.f);
    }

    int t = start + w;
    float4 kc, vc;
    if (t < end) {
        if (t == pos) {
            kc = *(const float4*)&g_qkv[b][QSIZE + kvh * HDIM + lane * 4];
            vc = *(const float4*)&g_qkv[b][QSIZE + KVSIZE + kvh * HDIM + lane * 4];
        } else {
            long o = (((long)sbt[(t - start) >> 4] * PG_BLK + (t & 15)) * NKVH + kvh) * HDIM;
            kc = *(const float4*)(k_cache + o + lane * 4);
            vc = *(const float4*)(v_cache + o + lane * 4);
        }
    }

    while (t < end) {
        int tn = t + 4;
        float4 kn, vn;
        if (tn < end) {                 // prefetch next iteration
            if (tn == pos) {
                kn = *(const float4*)&g_qkv[b][QSIZE + kvh * HDIM + lane * 4];
                vn = *(const float4*)&g_qkv[b][QSIZE + KVSIZE + kvh * HDIM + lane * 4];
            } else {
                long o = (((long)sbt[(tn - start) >> 4] * PG_BLK + (tn & 15)) * NKVH + kvh) * HDIM;
                kn = *(const float4*)(k_cache + o + lane * 4);
                vn = *(const float4*)(v_cache + o + lane * 4);
            }
        }

        float s4[GRP];
#pragma unroll
        for (int g = 0; g < GRP; g++) {
            float pd = kc.x * q[g].x + kc.y * q[g].y + kc.z * q[g].z + kc.w * q[g].w;
            pd += __shfl_xor_sync(0xffffffff, pd, 16);
            pd += __shfl_xor_sync(0xffffffff, pd, 8);
            pd += __shfl_xor_sync(0xffffffff, pd, 4);
            pd += __shfl_xor_sync(0xffffffff, pd, 2);
            pd += __shfl_xor_sync(0xffffffff, pd, 1);
            s4[g] = pd * scale;
        }
#pragma unroll
        for (int g = 0; g < GRP; g++) {
            float mn = fmaxf(m[g], s4[g]);
            float corr = __expf(m[g] - mn);
            float pr = __expf(s4[g] - mn);
            l[g] = l[g] * corr + pr;
            acc[g].x = acc[g].x * corr + pr * vc.x;
            acc[g].y = acc[g].y * corr + pr * vc.y;
            acc[g].z = acc[g].z * corr + pr * vc.z;
            acc[g].w = acc[g].w * corr + pr * vc.w;
            m[g] = mn;
        }
        kc = kn; vc = vn; t = tn;
    }

#pragma unroll
    for (int g = 0; g < GRP; g++) {
        if (lane == 0) { sm[w][g] = m[g]; sl[w][g] = l[g]; }
        *(float4*)&sacc[w][g][lane * 4] = acc[g];
    }
    __syncthreads();

    const int d = tid;
#pragma unroll
    for (int g = 0; g < GRP; g++) {
        float M = fmaxf(fmaxf(sm[0][g], sm[1][g]), fmaxf(sm[2][g], sm[3][g]));
        float L = 0.f, O = 0.f;
#pragma unroll
        for (int ww = 0; ww < 4; ww++) {
            float cc = __expf(sm[ww][g] - M);
            L += sl[ww][g] * cc;
            O += sacc[ww][g][d] * cc;
        }
        g_po[b][kvh][g][sp][d] = O;
        if (d == 0) { g_pm[b][kvh][g][sp] = M; g_pl[b][kvh][g][sp] = L; }
    }
}

// ---------------------------------------------------------------------------
// Split combine (LSE merge). grid=(NKVH, BATCH), 128 thr, predicated unroll.
// ---------------------------------------------------------------------------
__global__ __launch_bounds__(128)
void attn_combine(const int* __restrict__ ctxl) {
    const int kvh = blockIdx.x, b = blockIdx.y;
    const int ns = (ctxl[b] + SPLIT - 1) / SPLIT;
    const int d = threadIdx.x;

    for (int g = 0; g < GRP; g++) {
        float pm[NSPLIT], pl[NSPLIT], po[NSPLIT];
#pragma unroll
        for (int s = 0; s < NSPLIT; s++) {
            bool v = s < ns;
            pm[s] = v ? g_pm[b][kvh][g][s] : -INFINITY;
            pl[s] = v ? g_pl[b][kvh][g][s] : 0.f;
            po[s] = v ? g_po[b][kvh][g][s][d] : 0.f;
        }
        float M = -INFINITY;
#pragma unroll
        for (int s = 0; s < NSPLIT; s++) M = fmaxf(M, pm[s]);
        float L = 0.f, O = 0.f;
#pragma unroll
        for (int s = 0; s < NSPLIT; s++) {
            float cc = __expf(pm[s] - M);
            L += pl[s] * cc;
            O += po[s] * cc;
        }
        g_attn[b][(kvh * GRP + g) * HDIM + d] = O / L;
    }
}

// ---------------------------------------------------------------------------
// Epilogue: sum O-proj split-K partials + bias -> d_out
// ---------------------------------------------------------------------------
__global__ __launch_bounds__(256)
void oproj_epilogue(const float* __restrict__ b_o, float* __restrict__ out) {
    int i = blockIdx.x * 256 + threadIdx.x;
    float v = b_o[i & (HIDDEN - 1)];
    const float* base = &g_o_part[0][0][0];
#pragma unroll
    for (int p = 0; p < KSPLIT; p++) v += base[(long)p * BATCH * HIDDEN + i];
    out[i] = v;
}

// ---------------------------------------------------------------------------
// Launcher
// ---------------------------------------------------------------------------
extern "C" void kernel_launch(void* const* d_in, const int* in_sizes, int n_in,
                              void* d_out, int out_size) {
    const float* hidden   = (const float*)d_in[0];
    const float* W_qkv    = (const float*)d_in[1];
    const float* b_qkv    = (const float*)d_in[2];
    const float* W_o      = (const float*)d_in[3];
    const float* b_o      = (const float*)d_in[4];
    const float* k_cache  = (const float*)d_in[5];
    const float* v_cache  = (const float*)d_in[6];
    const int*   btables  = (const int*)d_in[7];
    const int*   ctx_lens = (const int*)d_in[8];
    float* out = (float*)d_out;

    float *qkv_part_ptr, *attn_ptr, *o_part_ptr;
    cudaGetSymbolAddress((void**)&qkv_part_ptr, g_qkv_part);
    cudaGetSymbolAddress((void**)&attn_ptr,     g_attn);
    cudaGetSymbolAddress((void**)&o_part_ptr,   g_o_part);

    gemm_skinny<<<dim3(QKVN / TBN, KSPLIT), 128>>>(hidden, W_qkv, qkv_part_ptr, HIDDEN, QKVN);
    qkv_combine_rope<<<dim3(8, BATCH), 256>>>(b_qkv, ctx_lens);
    attn_split<<<dim3(NSPLIT, NKVH, BATCH), 128>>>(k_cache, v_cache, btables, ctx_lens);
    attn_combine<<<dim3(NKVH, BATCH), 128>>>(ctx_lens);
    gemm_skinny<<<dim3(HIDDEN / TBN, KSPLIT), 128>>>(attn_ptr, W_o, o_part_ptr, HIDDEN, HIDDEN);
    oproj_epilogue<<<(BATCH * HIDDEN) / 256, 256>>>(b_o, out);
}